// round 10
// baseline (speedup 1.0000x reference)
#include <cuda_runtime.h>
#include <cuda_bf16.h>
#include <cstdint>

#define BB 16
#define DD 256
#define TT 2048
#define KK 8192
#define NN (BB*TT)          /* 32768 tokens  */
#define NQ (BB*DD*TT)       /* 8388608 elems */

typedef unsigned int uint;

// ---------------------------------------------------------------------------
// Scratch (static __device__ arrays: allocation-free per harness rules)
__device__ __align__(128) uint g_abf[NN * DD / 2];   // z as bf16 [n][256], 16MB
__device__ __align__(128) uint g_bbf[KK * DD / 2];   // emb as bf16 [k][256], 4MB
__device__ float g_embT[DD*KK];    // emb transposed [D][K] (for k_quant gather)
__device__ float g_enorm[KK];      // ||e_k||^2 (exact fp32)
__device__ float g_s1[NN];         // ||z_n||^2 (sequential-d fp32)
__device__ int   g_idx[NN];        // argmin per token
__device__ float g_partial[1024];  // loss partials

// ---------------------------------------------------------------------------
// helpers (all arch-neutral PTX: sm_80-era, compiles at compute_103)
__device__ __forceinline__ uint s2u(const void* p) {
    uint a;
    asm("{ .reg .u64 t; cvta.to.shared.u64 t, %1; cvt.u32.u64 %0, t; }"
        : "=r"(a) : "l"(p));
    return a;
}
__device__ __forceinline__ void cpa16(uint dst, const void* src) {
    asm volatile("cp.async.cg.shared.global [%0], [%1], 16;"
                 :: "r"(dst), "l"(src) : "memory");
}
__device__ __forceinline__ void cpcommit() {
    asm volatile("cp.async.commit_group;" ::: "memory");
}
__device__ __forceinline__ void cpwait1() {
    asm volatile("cp.async.wait_group 1;" ::: "memory");
}
__device__ __forceinline__ void cpwait0() {
    asm volatile("cp.async.wait_group 0;" ::: "memory");
}
__device__ __forceinline__ void ldm_x4(uint &r0, uint &r1, uint &r2, uint &r3, uint addr) {
    asm volatile("ldmatrix.sync.aligned.m8n8.x4.shared.b16 {%0,%1,%2,%3}, [%4];"
                 : "=r"(r0), "=r"(r1), "=r"(r2), "=r"(r3) : "r"(addr));
}
__device__ __forceinline__ void mma16816(float* c, const uint* a, uint b0, uint b1) {
    asm volatile("mma.sync.aligned.m16n8k16.row.col.f32.bf16.bf16.f32 "
                 "{%0,%1,%2,%3}, {%4,%5,%6,%7}, {%8,%9}, {%0,%1,%2,%3};"
                 : "+f"(c[0]), "+f"(c[1]), "+f"(c[2]), "+f"(c[3])
                 : "r"(a[0]), "r"(a[1]), "r"(a[2]), "r"(a[3]), "r"(b0), "r"(b1));
}
// order-preserving float<->uint (monotonic; atomicMin-able)
__device__ __forceinline__ uint encf(float f) {
    uint b = __float_as_uint(f);
    return (b & 0x80000000u) ? ~b : (b | 0x80000000u);
}
__device__ __forceinline__ float decf(uint u) {
    return (u & 0x80000000u) ? __uint_as_float(u & 0x7fffffffu)
                             : __uint_as_float(~u);
}

// ---------------------------------------------------------------------------
// emb [K,D] -> embT [D,K] (for k_quant gather)
__global__ void k_transpose(const float* __restrict__ emb) {
    __shared__ float tile[32][33];
    int k0 = blockIdx.x * 32, d0 = blockIdx.y * 32;
    int tx = threadIdx.x, ty = threadIdx.y;
    #pragma unroll
    for (int i = 0; i < 32; i += 8)
        tile[ty + i][tx] = emb[(size_t)(k0 + ty + i) * DD + d0 + tx];
    __syncthreads();
    #pragma unroll
    for (int i = 0; i < 32; i += 8)
        g_embT[(size_t)(d0 + ty + i) * KK + k0 + tx] = tile[tx][ty + i];
}

// per-code squared norms (UNCHANGED from the rel_err=0 kernel)
__global__ void k_norms(const float* __restrict__ emb) {
    int r = blockIdx.x * 8 + (threadIdx.x >> 5);
    int lane = threadIdx.x & 31;
    float s = 0.f;
    for (int i = lane; i < DD; i += 32) {
        float v = emb[(size_t)r * DD + i];
        s += v * v;
    }
    #pragma unroll
    for (int o = 16; o > 0; o >>= 1) s += __shfl_xor_sync(0xffffffffu, s, o);
    if (lane == 0) g_enorm[r] = s;
}

// z -> bf16 [n][256] row-major; also ||z||^2 sequential-d fp32 (reference order)
__global__ void k_prepA(const float* __restrict__ z) {
    int n = blockIdx.x * 128 + threadIdx.x;
    const float* zp = z + (size_t)(n >> 11) * DD * TT + (n & (TT - 1));
    uint* dst = g_abf + (size_t)n * 128;
    float s1 = 0.f;
    for (int d0 = 0; d0 < DD; d0 += 8) {
        float v[8];
        #pragma unroll
        for (int u = 0; u < 8; u++) v[u] = zp[(size_t)(d0 + u) * TT];
        #pragma unroll
        for (int u = 0; u < 8; u++) s1 += v[u] * v[u];
        uint pk[4];
        #pragma unroll
        for (int u = 0; u < 4; u++) {
            __nv_bfloat162 h = __floats2bfloat162_rn(v[2 * u], v[2 * u + 1]);
            pk[u] = *(uint*)&h;
        }
        *(uint4*)(dst + d0 / 2) = *(uint4*)pk;
    }
    g_s1[n] = s1;
}

// emb -> bf16 [k][256] row-major
__global__ void k_prepB(const float* __restrict__ emb) {
    int k = blockIdx.x * 128 + threadIdx.x;
    const float* ep = emb + (size_t)k * DD;
    uint* dst = g_bbf + (size_t)k * 128;
    for (int d0 = 0; d0 < DD; d0 += 8) {
        float v[8];
        #pragma unroll
        for (int u = 0; u < 8; u++) v[u] = ep[d0 + u];
        uint pk[4];
        #pragma unroll
        for (int u = 0; u < 4; u++) {
            __nv_bfloat162 h = __floats2bfloat162_rn(v[2 * u], v[2 * u + 1]);
            pk[u] = *(uint*)&h;
        }
        *(uint4*)(dst + d0 / 2) = *(uint4*)pk;
    }
}

// ---------------------------------------------------------------------------
// Pass-1 HMMA + candidate collect + fused exact fp32 rescue.
// Block: 128 tokens x all 8192 codes. 256 threads = 8 warps (4 m x 2 n).
// Smem: A[4 chunks][128 rows][64 bf16] swizzled (64KB), B double-buf (32KB),
//       ens 512B, bestu 512B, cnt 512B, cand 128*48*4 (24KB)
#define SA     0
#define SBUF   65536
#define SENS   98304
#define SBEST  98816
#define SCNT   99328
#define SCAND  99840
#define STOT   124416
#define CAP    48
#define MARGIN 5e-4f

__device__ __forceinline__ void loadB_stage(uint sb, int tid, int s, int buf) {
    int tn = s >> 2, ch = s & 3;
    const char* bsrc = (const char*)g_bbf + (size_t)tn * 65536;
    #pragma unroll
    for (int it = 0; it < 4; it++) {
        int i = tid + it * 256;
        int row = i >> 3, c = i & 7;
        uint dst = sb + SBUF + buf * 16384 + row * 128 + (((c ^ (row & 7)) << 4));
        cpa16(dst, bsrc + row * 512 + ch * 128 + c * 16);
    }
}

__global__ __launch_bounds__(256, 1)
void k_argmin_mma(const float* __restrict__ z, const float* __restrict__ emb,
                  float* __restrict__ idxOutF, int writeIdx) {
    extern __shared__ char sm[];
    uint sb = s2u(sm);
    int tid = threadIdx.x, lane = tid & 31, wid = tid >> 5;
    int wm = wid & 3, wn = wid >> 2;
    int g = lane >> 2, tg = lane & 3;
    int tile = blockIdx.x;

    uint*  bestuS = (uint*)(sm + SBEST);
    int*   cntS   = (int*)(sm + SCNT);
    int*   candS  = (int*)(sm + SCAND);
    float* ensS   = (float*)(sm + SENS);

    if (tid < 128) { bestuS[tid] = encf(3.4e38f); cntS[tid] = 0; }

    // A: 4096 x 16B chunks, swizzled rows of 128B (chunk idx c ^= row&7)
    {
        const char* asrc = (const char*)g_abf + (size_t)tile * 65536;
        #pragma unroll
        for (int it = 0; it < 16; it++) {
            int i = tid + it * 256;
            int ch = i >> 10, row = (i >> 3) & 127, c = i & 7;
            uint dst = sb + SA + ch * 16384 + row * 128 + (((c ^ (row & 7)) << 4));
            cpa16(dst, asrc + row * 512 + ch * 128 + c * 16);
        }
        cpcommit();
    }
    loadB_stage(sb, tid, 0, 0);
    cpcommit();

    float acc[2][8][4];
    #pragma unroll
    for (int mt = 0; mt < 2; mt++)
        #pragma unroll
        for (int nt = 0; nt < 8; nt++)
            #pragma unroll
            for (int e = 0; e < 4; e++) acc[mt][nt][e] = 0.f;

    for (int s = 0; s < 256; s++) {
        __syncthreads();                        // everyone done with compute(s-1)
        if (s + 1 < 256) { loadB_stage(sb, tid, s + 1, (s + 1) & 1); cpcommit(); }
        if (s + 1 < 256) cpwait1(); else cpwait0();
        __syncthreads();                        // stage-s smem visible

        if ((s & 3) == 0 && tid < 128)
            ensS[tid] = g_enorm[(s >> 2) * 128 + tid];

        uint abase = sb + SA + (s & 3) * 16384;
        uint bbase = sb + SBUF + (s & 1) * 16384;
        #pragma unroll
        for (int ks = 0; ks < 4; ks++) {
            int ca = ks * 2 + (lane >> 4);      // 16B-chunk index for this lane
            uint af[2][4];
            #pragma unroll
            for (int mt = 0; mt < 2; mt++) {
                int row = wm * 32 + mt * 16 + (lane & 15);
                ldm_x4(af[mt][0], af[mt][1], af[mt][2], af[mt][3],
                       abase + row * 128 + (((ca ^ (row & 7)) << 4)));
            }
            uint bf[4][4];
            #pragma unroll
            for (int p = 0; p < 4; p++) {
                int row = wn * 64 + p * 16 + (lane & 15);
                ldm_x4(bf[p][0], bf[p][1], bf[p][2], bf[p][3],
                       bbase + row * 128 + (((ca ^ (row & 7)) << 4)));
            }
            #pragma unroll
            for (int mt = 0; mt < 2; mt++)
                #pragma unroll
                for (int p = 0; p < 4; p++) {
                    mma16816(acc[mt][2 * p],     af[mt], bf[p][0], bf[p][2]);
                    mma16816(acc[mt][2 * p + 1], af[mt], bf[p][1], bf[p][3]);
                }
        }

        if ((s & 3) == 3) {                     // epilogue for code tile T
            int T = s >> 2;
            int kbase = T * 128 + wn * 64;
            #pragma unroll
            for (int mt = 0; mt < 2; mt++)
                #pragma unroll
                for (int h = 0; h < 2; h++) {
                    int tok = wm * 32 + mt * 16 + h * 8 + g;
                    float thr = decf(bestuS[tok]) + MARGIN;
                    #pragma unroll
                    for (int nt = 0; nt < 8; nt++)
                        #pragma unroll
                        for (int e = 0; e < 2; e++) {
                            int kl = wn * 64 + nt * 8 + tg * 2 + e;
                            float da = fmaf(-2.f, acc[mt][nt][h * 2 + e], ensS[kl]);
                            if (da < thr) {
                                int pos = atomicAdd(&cntS[tok], 1);
                                if (pos < CAP) candS[tok * CAP + pos] = kbase + nt * 8 + tg * 2 + e;
                                if (da + MARGIN < thr) {
                                    thr = da + MARGIN;
                                    atomicMin(&bestuS[tok], encf(da));
                                }
                            }
                            acc[mt][nt][h * 2 + e] = 0.f;
                        }
                }
        }
    }
    __syncthreads();

    // -------- exact fp32 rescue (reference rounding), 2 threads per token
    float* rD = (float*)(sm + SBUF);            // B buffers now free
    int*   rI = (int*)(sm + SBUF + 1024);
    {
        int r = tid & 127, part = tid >> 7;
        int n = tile * 128 + r;
        const float* zp = z + (size_t)(n >> 11) * DD * TT + (n & (TT - 1));
        float s1 = g_s1[n];
        int cnt = cntS[r];
        float bestd = 3.4e38f; int besti = 0x7fffffff;
        if (cnt <= CAP) {
            for (int q = part; q < cnt; q += 2) {
                int k = candS[r * CAP + q];
                const float* ep = emb + (size_t)k * DD;
                float dot = 0.f;
                #pragma unroll 8
                for (int d = 0; d < DD; d++) dot += zp[(size_t)d * TT] * ep[d];
                float c = s1 + g_enorm[k];
                float dist = c - 2.0f * dot;    // == fl(c - 2*dot), *2 exact
                if (dist < bestd || (dist == bestd && k < besti)) { bestd = dist; besti = k; }
            }
        } else {                                // overflow: exact full scan
            for (int k = part; k < KK; k += 2) {
                const float* ep = emb + (size_t)k * DD;
                float dot = 0.f;
                #pragma unroll 8
                for (int d = 0; d < DD; d++) dot += zp[(size_t)d * TT] * ep[d];
                float c = s1 + g_enorm[k];
                float dist = c - 2.0f * dot;
                if (dist < bestd || (dist == bestd && k < besti)) { bestd = dist; besti = k; }
            }
        }
        rD[tid] = bestd; rI[tid] = besti;
    }
    __syncthreads();
    if (tid < 128) {
        float d0 = rD[tid], d1 = rD[tid + 128];
        int   i0 = rI[tid], i1 = rI[tid + 128];
        int best = (d1 < d0 || (d1 == d0 && i1 < i0)) ? i1 : i0;
        int n = tile * 128 + tid;
        g_idx[n] = best;
        if (writeIdx) idxOutF[n] = (float)best;
    }
}

// ---------------------------------------------------------------------------
// Gather + straight-through output + loss partials (deterministic order)
__global__ void k_quant(const float* __restrict__ z, float* __restrict__ out) {
    __shared__ float red[256];
    size_t base = (size_t)blockIdx.x * 8192;
    float ls = 0.f;
    #pragma unroll 4
    for (int j = 0; j < 32; j++) {
        size_t i = base + threadIdx.x + (size_t)j * 256;
        int t = (int)(i & (TT - 1));
        int d = (int)((i >> 11) & (DD - 1));
        int b = (int)(i >> 19);
        int n = b * TT + t;
        float zv = z[i];
        float q  = g_embT[(size_t)d * KK + g_idx[n]];
        float diff = q - zv;
        out[i] = zv + diff;                // z + (q - z): reference rounding
        ls += diff * diff;
    }
    red[threadIdx.x] = ls;
    __syncthreads();
    #pragma unroll
    for (int o = 128; o > 0; o >>= 1) {
        if (threadIdx.x < o) red[threadIdx.x] += red[threadIdx.x + o];
        __syncthreads();
    }
    if (threadIdx.x == 0) g_partial[blockIdx.x] = red[0];
}

__global__ void k_final(float* out_loss, int doWrite) {
    __shared__ float red[256];
    float s = 0.f;
    #pragma unroll
    for (int j = 0; j < 4; j++) s += g_partial[threadIdx.x + j * 256];
    red[threadIdx.x] = s;
    __syncthreads();
    #pragma unroll
    for (int o = 128; o > 0; o >>= 1) {
        if (threadIdx.x < o) red[threadIdx.x] += red[threadIdx.x + o];
        __syncthreads();
    }
    if (threadIdx.x == 0 && doWrite)
        out_loss[0] = 1.25f * (red[0] / (float)NQ);
}

// ---------------------------------------------------------------------------
extern "C" void kernel_launch(void* const* d_in, const int* in_sizes, int n_in,
                              void* d_out, int out_size) {
    const float* z   = (const float*)d_in[0];
    const float* emb = (const float*)d_in[1];
    if (n_in >= 2 && in_sizes[0] == KK * DD && in_sizes[1] == NQ) {
        const float* tmp = z; z = emb; emb = tmp;   // defensive input-order swap
    }
    float* out = (float*)d_out;
    int writeTail = (out_size >= NQ + 1 + NN) ? 1 : 0;

    static int attrSet = 0;
    if (!attrSet) {
        cudaFuncSetAttribute(k_argmin_mma,
                             cudaFuncAttributeMaxDynamicSharedMemorySize, STOT);
        attrSet = 1;
    }

    k_transpose<<<dim3(KK / 32, DD / 32), dim3(32, 8)>>>(emb);
    k_norms<<<KK / 8, 256>>>(emb);
    k_prepA<<<NN / 128, 128>>>(z);
    k_prepB<<<KK / 128, 128>>>(emb);
    k_argmin_mma<<<NN / 128, 256, STOT>>>(z, emb, out + NQ + 1, writeTail);
    k_quant<<<1024, 256>>>(z, out);
    k_final<<<1, 256>>>(out + NQ, writeTail);
}

// round 12
// speedup vs baseline: 1.9007x; 1.9007x over previous
#include <cuda_runtime.h>
#include <cstdint>

#define BB 16
#define DD 256
#define TT 2048
#define KK 8192
#define NN (BB*TT)          /* 32768 tokens  */
#define NQ (BB*DD*TT)       /* 8388608 elems */
#define NCH 64              /* 64 uint chunks of 4 int8 per D=256 */

typedef unsigned int uint;

// ---------------------------------------------------------------------------
// Scratch (static __device__ arrays: allocation-free per harness rules)
__device__ __align__(128) uint g_qzT[NCH * NN];   // int8 z, [chunk][token], 8MB
__device__ __align__(128) uint g_qeT[NCH * KK];   // int8 emb, [chunk][code], 2MB
__device__ float g_embT[DD*KK];    // emb transposed [D][K] (for k_quant gather)
__device__ float g_enorm[KK];      // ||e_k||^2 (exact fp32)
__device__ float g_s1[NN];         // ||z_n||^2 (sequential-d fp32)
__device__ float g_f2[NN];         // 2*sz_n*se/127^2
__device__ uint  g_seU;            // max|emb| as float bits
__device__ int   g_idx[NN];        // argmin per token
__device__ float g_partial[1024];  // loss partials

// signed dp4a via PTX: 4 int8 MACs into s32 (unambiguous, fixed-pipe)
__device__ __forceinline__ int dp4a_s(uint a, uint b, int c) {
    int d;
    asm("dp4a.s32.s32 %0, %1, %2, %3;" : "=r"(d) : "r"(a), "r"(b), "r"(c));
    return d;
}

// order-preserving float<->uint (monotonic; atomicMin-able)
__device__ __forceinline__ uint encf(float f) {
    uint b = __float_as_uint(f);
    return (b & 0x80000000u) ? ~b : (b | 0x80000000u);
}
__device__ __forceinline__ float decf(uint u) {
    return (u & 0x80000000u) ? __uint_as_float(u & 0x7fffffffu)
                             : __uint_as_float(~u);
}

// ---------------------------------------------------------------------------
// emb [K,D] -> embT [D,K] (for k_quant gather)
__global__ void k_transpose(const float* __restrict__ emb) {
    __shared__ float tile[32][33];
    int k0 = blockIdx.x * 32, d0 = blockIdx.y * 32;
    int tx = threadIdx.x, ty = threadIdx.y;
    #pragma unroll
    for (int i = 0; i < 32; i += 8)
        tile[ty + i][tx] = emb[(size_t)(k0 + ty + i) * DD + d0 + tx];
    __syncthreads();
    #pragma unroll
    for (int i = 0; i < 32; i += 8)
        g_embT[(size_t)(d0 + ty + i) * KK + k0 + tx] = tile[tx][ty + i];
}

// per-code squared norms (UNCHANGED from the rel_err=0 kernel)
__global__ void k_norms(const float* __restrict__ emb) {
    int r = blockIdx.x * 8 + (threadIdx.x >> 5);
    int lane = threadIdx.x & 31;
    float s = 0.f;
    for (int i = lane; i < DD; i += 32) {
        float v = emb[(size_t)r * DD + i];
        s += v * v;
    }
    #pragma unroll
    for (int o = 16; o > 0; o >>= 1) s += __shfl_xor_sync(0xffffffffu, s, o);
    if (lane == 0) g_enorm[r] = s;
}

__global__ void k_zero() { g_seU = 0u; }

// global max|emb| (max is order-invariant -> deterministic)
__global__ void k_semax(const float* __restrict__ emb) {
    __shared__ float red[256];
    float m = 0.f;
    for (int i = blockIdx.x * 256 + threadIdx.x; i < KK * DD; i += 256 * 256)
        m = fmaxf(m, fabsf(emb[i]));
    red[threadIdx.x] = m;
    __syncthreads();
    #pragma unroll
    for (int o = 128; o > 0; o >>= 1) {
        if (threadIdx.x < o) red[threadIdx.x] = fmaxf(red[threadIdx.x], red[threadIdx.x + o]);
        __syncthreads();
    }
    if (threadIdx.x == 0) atomicMax(&g_seU, __float_as_uint(red[0]));
}

// z -> int8 [chunk][token]; ||z||^2 sequential-d fp32 (reference order); f2 scale
__global__ void k_prepA(const float* __restrict__ z) {
    int n = blockIdx.x * 128 + threadIdx.x;
    const float* zp = z + (size_t)(n >> 11) * DD * TT + (n & (TT - 1));
    float se = __uint_as_float(g_seU);
    float s1 = 0.f, mx = 0.f;
    for (int d0 = 0; d0 < DD; d0 += 8) {
        float v[8];
        #pragma unroll
        for (int u = 0; u < 8; u++) v[u] = zp[(size_t)(d0 + u) * TT];
        #pragma unroll
        for (int u = 0; u < 8; u++) s1 += v[u] * v[u];
        #pragma unroll
        for (int u = 0; u < 8; u++) mx = fmaxf(mx, fabsf(v[u]));
    }
    float sz = fmaxf(mx, 1e-30f);
    float qs = 127.0f / sz;
    for (int c = 0; c < NCH; c++) {
        int q[4];
        #pragma unroll
        for (int u = 0; u < 4; u++)
            q[u] = __float2int_rn(zp[(size_t)(c * 4 + u) * TT] * qs);
        uint pk = (uint)(q[0] & 255) | ((uint)(q[1] & 255) << 8)
                | ((uint)(q[2] & 255) << 16) | ((uint)(q[3] & 255) << 24);
        g_qzT[(size_t)c * NN + n] = pk;
    }
    g_s1[n] = s1;
    g_f2[n] = 2.0f * sz * se / 16129.0f;     // 2*sz*se/127^2
}

// emb -> int8 [chunk][code] with global scale
__global__ void k_prepB(const float* __restrict__ emb) {
    int k = blockIdx.x * 128 + threadIdx.x;
    const float* ep = emb + (size_t)k * DD;
    float qs = 127.0f / __uint_as_float(g_seU);
    for (int c = 0; c < NCH; c++) {
        int q[4];
        #pragma unroll
        for (int u = 0; u < 4; u++)
            q[u] = __float2int_rn(ep[c * 4 + u] * qs);
        uint pk = (uint)(q[0] & 255) | ((uint)(q[1] & 255) << 8)
                | ((uint)(q[2] & 255) << 16) | ((uint)(q[3] & 255) << 24);
        g_qeT[(size_t)c * KK + k] = pk;
    }
}

// ---------------------------------------------------------------------------
// dp4a pass-1 (exact int32 dots of quantized inputs) + candidates + exact
// fp32 rescue. 128 tokens x 128 codes tile, 8x8 per thread (R2 skeleton).
#define CAP 24
#define MARGIN 4e-4f

__global__ __launch_bounds__(256, 2)
void k_argmin_i8(const float* __restrict__ z, const float* __restrict__ emb,
                 float* __restrict__ idxOutF, int writeIdx) {
    __shared__ uint  As[8][128];
    __shared__ uint  Bs[8][128];
    __shared__ float ens[128];
    __shared__ float f2s[128];
    __shared__ uint  bestuS[128];
    __shared__ int   cntS[128];
    __shared__ int   candS[128 * CAP];
    __shared__ float rD[256];
    __shared__ int   rI[256];

    int tid = threadIdx.x;
    int ty = tid >> 4, tx = tid & 15;
    int tile = blockIdx.x;
    int t0 = tile * 128;                 // global token base

    if (tid < 128) {
        bestuS[tid] = encf(3.4e38f);
        cntS[tid] = 0;
        f2s[tid] = g_f2[t0 + tid];
    }
    int ldd = tid >> 5;                  // 0..7
    int lc4 = (tid & 31) << 2;           // 0..124

    for (int ct = 0; ct < KK / 128; ct++) {
        int k0 = ct * 128;
        int acc[8][8];
        #pragma unroll
        for (int i = 0; i < 8; i++)
            #pragma unroll
            for (int j = 0; j < 8; j++) acc[i][j] = 0;

        __syncthreads();                 // prior epilogue done (ens, bestuS races)
        if (tid < 128) ens[tid] = g_enorm[k0 + tid];

        // prefetch round 0
        uint4 pa = *(const uint4*)&g_qzT[(size_t)ldd * NN + t0 + lc4];
        uint4 pb = *(const uint4*)&g_qeT[(size_t)ldd * KK + k0 + lc4];

        for (int rc = 0; rc < 8; rc++) {
            __syncthreads();             // prior round's compute done
            *(uint4*)&As[ldd][lc4] = pa;
            *(uint4*)&Bs[ldd][lc4] = pb;
            __syncthreads();             // tile visible
            if (rc < 7) {
                int c0 = (rc + 1) * 8;
                pa = *(const uint4*)&g_qzT[(size_t)(c0 + ldd) * NN + t0 + lc4];
                pb = *(const uint4*)&g_qeT[(size_t)(c0 + ldd) * KK + k0 + lc4];
            }
            #pragma unroll
            for (int kk = 0; kk < 8; kk++) {
                uint a[8], b[8];
                *(uint4*)(a)     = *(uint4*)&As[kk][ty * 8];
                *(uint4*)(a + 4) = *(uint4*)&As[kk][ty * 8 + 4];
                *(uint4*)(b)     = *(uint4*)&Bs[kk][tx * 8];
                *(uint4*)(b + 4) = *(uint4*)&Bs[kk][tx * 8 + 4];
                #pragma unroll
                for (int i = 0; i < 8; i++)
                    #pragma unroll
                    for (int j = 0; j < 8; j++)
                        acc[i][j] = dp4a_s(a[i], b[j], acc[i][j]);
            }
        }

        // epilogue pass 1: per-token running-best update (shared, monotone)
        #pragma unroll
        for (int i = 0; i < 8; i++) {
            int tok = ty * 8 + i;
            float fi = f2s[tok];
            float lmin = 3.4e38f;
            #pragma unroll
            for (int j = 0; j < 8; j++) {
                float da = fmaf(-fi, (float)acc[i][j], ens[tx * 8 + j]);
                if (da < lmin) lmin = da;
            }
            if (lmin < decf(bestuS[tok])) atomicMin(&bestuS[tok], encf(lmin));
        }
        __syncthreads();                 // bests visible to pass 2

        // epilogue pass 2: append codes within MARGIN of the global best-so-far
        #pragma unroll
        for (int i = 0; i < 8; i++) {
            int tok = ty * 8 + i;
            float fi = f2s[tok];
            float thr = decf(bestuS[tok]) + MARGIN;
            #pragma unroll
            for (int j = 0; j < 8; j++) {
                float da = fmaf(-fi, (float)acc[i][j], ens[tx * 8 + j]);
                if (da < thr) {
                    int pos = atomicAdd(&cntS[tok], 1);
                    if (pos < CAP) candS[tok * CAP + pos] = k0 + tx * 8 + j;
                }
            }
        }
    }
    __syncthreads();

    // -------- exact fp32 rescue (reference rounding), 2 threads per token
    {
        int r = tid & 127, part = tid >> 7;
        int n = t0 + r;
        const float* zp = z + (size_t)(n >> 11) * DD * TT + (n & (TT - 1));
        float s1 = g_s1[n];
        int cnt = cntS[r];
        float bestd = 3.4e38f; int besti = 0x7fffffff;
        if (cnt <= CAP) {
            for (int q = part; q < cnt; q += 2) {
                int k = candS[r * CAP + q];
                const float* ep = emb + (size_t)k * DD;
                float dot = 0.f;
                #pragma unroll 8
                for (int d = 0; d < DD; d++) dot += zp[(size_t)d * TT] * ep[d];
                float c = s1 + g_enorm[k];
                float dist = c - 2.0f * dot;     // == fl(c - 2*dot), *2 exact
                if (dist < bestd || (dist == bestd && k < besti)) { bestd = dist; besti = k; }
            }
        } else {                                  // overflow: exact full scan
            for (int k = part; k < KK; k += 2) {
                const float* ep = emb + (size_t)k * DD;
                float dot = 0.f;
                #pragma unroll 8
                for (int d = 0; d < DD; d++) dot += zp[(size_t)d * TT] * ep[d];
                float c = s1 + g_enorm[k];
                float dist = c - 2.0f * dot;
                if (dist < bestd || (dist == bestd && k < besti)) { bestd = dist; besti = k; }
            }
        }
        rD[tid] = bestd; rI[tid] = besti;
    }
    __syncthreads();
    if (tid < 128) {
        float d0 = rD[tid], d1 = rD[tid + 128];
        int   i0 = rI[tid], i1 = rI[tid + 128];
        int best = (d1 < d0 || (d1 == d0 && i1 < i0)) ? i1 : i0;
        int n = t0 + tid;
        g_idx[n] = best;
        if (writeIdx) idxOutF[n] = (float)best;
    }
}

// ---------------------------------------------------------------------------
// Gather + straight-through output + loss partials (deterministic order)
__global__ void k_quant(const float* __restrict__ z, float* __restrict__ out) {
    __shared__ float red[256];
    size_t base = (size_t)blockIdx.x * 8192;
    float ls = 0.f;
    #pragma unroll 4
    for (int j = 0; j < 32; j++) {
        size_t i = base + threadIdx.x + (size_t)j * 256;
        int t = (int)(i & (TT - 1));
        int d = (int)((i >> 11) & (DD - 1));
        int b = (int)(i >> 19);
        int n = b * TT + t;
        float zv = z[i];
        float q  = g_embT[(size_t)d * KK + g_idx[n]];
        float diff = q - zv;
        out[i] = zv + diff;                // z + (q - z): reference rounding
        ls += diff * diff;
    }
    red[threadIdx.x] = ls;
    __syncthreads();
    #pragma unroll
    for (int o = 128; o > 0; o >>= 1) {
        if (threadIdx.x < o) red[threadIdx.x] += red[threadIdx.x + o];
        __syncthreads();
    }
    if (threadIdx.x == 0) g_partial[blockIdx.x] = red[0];
}

__global__ void k_final(float* out_loss, int doWrite) {
    __shared__ float red[256];
    float s = 0.f;
    #pragma unroll
    for (int j = 0; j < 4; j++) s += g_partial[threadIdx.x + j * 256];
    red[threadIdx.x] = s;
    __syncthreads();
    #pragma unroll
    for (int o = 128; o > 0; o >>= 1) {
        if (threadIdx.x < o) red[threadIdx.x] += red[threadIdx.x + o];
        __syncthreads();
    }
    if (threadIdx.x == 0 && doWrite)
        out_loss[0] = 1.25f * (red[0] / (float)NQ);
}

// ---------------------------------------------------------------------------
extern "C" void kernel_launch(void* const* d_in, const int* in_sizes, int n_in,
                              void* d_out, int out_size) {
    const float* z   = (const float*)d_in[0];
    const float* emb = (const float*)d_in[1];
    if (n_in >= 2 && in_sizes[0] == KK * DD && in_sizes[1] == NQ) {
        const float* tmp = z; z = emb; emb = tmp;   // defensive input-order swap
    }
    float* out = (float*)d_out;
    int writeTail = (out_size >= NQ + 1 + NN) ? 1 : 0;

    k_transpose<<<dim3(KK / 32, DD / 32), dim3(32, 8)>>>(emb);
    k_norms<<<KK / 8, 256>>>(emb);
    k_zero<<<1, 1>>>();
    k_semax<<<256, 256>>>(emb);
    k_prepA<<<NN / 128, 128>>>(z);
    k_prepB<<<KK / 128, 128>>>(emb);
    k_argmin_i8<<<NN / 128, 256>>>(z, emb, out + NQ + 1, writeTail);
    k_quant<<<1024, 256>>>(z, out);
    k_final<<<1, 256>>>(out + NQ, writeTail);
}

// round 13
// speedup vs baseline: 16.2342x; 8.5410x over previous
#include <cuda_runtime.h>
#include <cuda_fp16.h>
#include <cstdint>

#define BB 16
#define DD 256
#define TT 2048
#define KK 8192
#define NN (BB*TT)          /* 32768 tokens  */
#define NQ (BB*DD*TT)       /* 8388608 elems */

typedef unsigned int uint;

// ---------------------------------------------------------------------------
// Scratch (static __device__ arrays: allocation-free per harness rules)
__device__ __align__(128) __half g_zh[DD * NN];       // 16MB: z scaled fp16, [d][token]
__device__ __align__(128) uint   g_eh[DD * KK / 2];   //  4MB: emb scaled fp16 pairs, [d][kpair]
__device__ float g_embT[DD*KK];    // emb transposed [D][K] (for k_quant + prepB)
__device__ float g_enorm[KK];      // ||e_k||^2 (exact fp32)
__device__ float g_s1[NN];         // ||z_n||^2 (sequential-d fp32)
__device__ float g_f2[NN];         // 2*sz_n*se
__device__ uint  g_seU;            // max|emb| as float bits
__device__ int   g_idx[NN];        // argmin per token
__device__ float g_partial[1024];  // loss partials

// order-preserving float<->uint (monotonic; atomicMin-able)
__device__ __forceinline__ uint encf(float f) {
    uint b = __float_as_uint(f);
    return (b & 0x80000000u) ? ~b : (b | 0x80000000u);
}
__device__ __forceinline__ float decf(uint u) {
    return (u & 0x80000000u) ? __uint_as_float(u & 0x7fffffffu)
                             : __uint_as_float(~u);
}

// ---------------------------------------------------------------------------
// emb [K,D] -> embT [D,K]
__global__ void k_transpose(const float* __restrict__ emb) {
    __shared__ float tile[32][33];
    int k0 = blockIdx.x * 32, d0 = blockIdx.y * 32;
    int tx = threadIdx.x, ty = threadIdx.y;
    #pragma unroll
    for (int i = 0; i < 32; i += 8)
        tile[ty + i][tx] = emb[(size_t)(k0 + ty + i) * DD + d0 + tx];
    __syncthreads();
    #pragma unroll
    for (int i = 0; i < 32; i += 8)
        g_embT[(size_t)(d0 + ty + i) * KK + k0 + tx] = tile[tx][ty + i];
}

// per-code squared norms (UNCHANGED from the rel_err=0 kernel)
__global__ void k_norms(const float* __restrict__ emb) {
    int r = blockIdx.x * 8 + (threadIdx.x >> 5);
    int lane = threadIdx.x & 31;
    float s = 0.f;
    for (int i = lane; i < DD; i += 32) {
        float v = emb[(size_t)r * DD + i];
        s += v * v;
    }
    #pragma unroll
    for (int o = 16; o > 0; o >>= 1) s += __shfl_xor_sync(0xffffffffu, s, o);
    if (lane == 0) g_enorm[r] = s;
}

__global__ void k_zero() { g_seU = 0u; }

// global max|emb| (max is order-invariant -> deterministic)
__global__ void k_semax(const float* __restrict__ emb) {
    __shared__ float red[256];
    float m = 0.f;
    for (int i = blockIdx.x * 256 + threadIdx.x; i < KK * DD; i += 256 * 256)
        m = fmaxf(m, fabsf(emb[i]));
    red[threadIdx.x] = m;
    __syncthreads();
    #pragma unroll
    for (int o = 128; o > 0; o >>= 1) {
        if (threadIdx.x < o) red[threadIdx.x] = fmaxf(red[threadIdx.x], red[threadIdx.x + o]);
        __syncthreads();
    }
    if (threadIdx.x == 0) atomicMax(&g_seU, __float_as_uint(red[0]));
}

// z -> scaled fp16 [d][token]; ||z||^2 sequential-d fp32 (reference order); f2 scale
__global__ void k_prepA(const float* __restrict__ z) {
    int n = blockIdx.x * 128 + threadIdx.x;
    const float* zp = z + (size_t)(n >> 11) * DD * TT + (n & (TT - 1));
    float se = __uint_as_float(g_seU);
    float s1 = 0.f, mx = 0.f;
    for (int d0 = 0; d0 < DD; d0 += 8) {
        float v[8];
        #pragma unroll
        for (int u = 0; u < 8; u++) v[u] = zp[(size_t)(d0 + u) * TT];
        #pragma unroll
        for (int u = 0; u < 8; u++) s1 += v[u] * v[u];
        #pragma unroll
        for (int u = 0; u < 8; u++) mx = fmaxf(mx, fabsf(v[u]));
    }
    float sz = fmaxf(mx, 1e-30f);
    float qs = 1.0f / sz;
    for (int d = 0; d < DD; d++)
        g_zh[(size_t)d * NN + n] = __float2half_rn(zp[(size_t)d * TT] * qs);
    g_s1[n] = s1;
    g_f2[n] = 2.0f * sz * se;
}

// emb -> scaled fp16 pairs [d][kpair] (reads embT: coalesced)
__global__ void k_prepB(const float* /*emb*/) {
    int jp = blockIdx.x * 128 + threadIdx.x;       // 0..4095 code pairs
    float qs = 1.0f / __uint_as_float(g_seU);
    for (int d = 0; d < DD; d++) {
        float e0 = g_embT[(size_t)d * KK + 2 * jp];
        float e1 = g_embT[(size_t)d * KK + 2 * jp + 1];
        __half2 h = __floats2half2_rn(e0 * qs, e1 * qs);
        g_eh[(size_t)d * (KK / 2) + jp] = *(uint*)&h;
    }
}

// ---------------------------------------------------------------------------
// HFMA2 pass-1 (fp16x2 packed MACs, phase-promoted to fp32) + candidates +
// exact fp32 rescue. 128 tokens x 128 codes tile, 8x8 per thread.
#define CAP 32
#define MARGIN 2.5e-4f

__global__ __launch_bounds__(256, 1)
void k_argmin_h(const float* __restrict__ z, const float* __restrict__ emb,
                float* __restrict__ idxOutF, int writeIdx) {
    __shared__ uint  As[8][64];        // 8 d x 128 tokens (halves)
    __shared__ uint  Bs[8][64];        // 8 d x 64 code-pairs
    __shared__ float ens[128];
    __shared__ float f2s[128];
    __shared__ uint  bestuS[128];
    __shared__ int   cntS[128];
    __shared__ int   candS[128 * CAP];
    __shared__ float rD[256];
    __shared__ int   rI[256];

    int tid = threadIdx.x;
    int ty = tid >> 4, tx = tid & 15;
    int tile = blockIdx.x;
    int t0 = tile * 128;                 // global token base

    if (tid < 128) {
        bestuS[tid] = encf(3.4e38f);
        cntS[tid] = 0;
        f2s[tid] = g_f2[t0 + tid];
    }
    int ldd = tid >> 5;                  // 0..7 (d row within chunk)
    int lcu = (tid & 31) * 2;            // uint col 0..62

    const uint* ga = (const uint*)g_zh;  // [d][NN/2] uints

    for (int ct = 0; ct < KK / 128; ct++) {
        int k0 = ct * 128;
        __half2 acc2[8][4];
        float accf[8][8];
        #pragma unroll
        for (int i = 0; i < 8; i++) {
            #pragma unroll
            for (int jp = 0; jp < 4; jp++) acc2[i][jp] = __float2half2_rn(0.f);
            #pragma unroll
            for (int j = 0; j < 8; j++) accf[i][j] = 0.f;
        }

        __syncthreads();                 // prior epilogue done (ens, bestuS races)
        if (tid < 128) ens[tid] = g_enorm[k0 + tid];

        // prefetch chunk 0
        uint2 pa = *(const uint2*)&ga[(size_t)ldd * (NN / 2) + (t0 >> 1) + lcu];
        uint2 pb = *(const uint2*)&g_eh[(size_t)ldd * (KK / 2) + (k0 >> 1) + lcu];

        for (int dc = 0; dc < 32; dc++) {
            __syncthreads();             // prior chunk's compute done
            *(uint2*)&As[ldd][lcu] = pa;
            *(uint2*)&Bs[ldd][lcu] = pb;
            __syncthreads();             // tile visible
            if (dc < 31) {
                int r0 = (dc + 1) * 8 + ldd;
                pa = *(const uint2*)&ga[(size_t)r0 * (NN / 2) + (t0 >> 1) + lcu];
                pb = *(const uint2*)&g_eh[(size_t)r0 * (KK / 2) + (k0 >> 1) + lcu];
            }
            #pragma unroll
            for (int kk = 0; kk < 8; kk++) {
                uint4 av = *(uint4*)&As[kk][ty * 4];   // 8 tokens (halves)
                uint4 bv = *(uint4*)&Bs[kk][tx * 4];   // 8 codes (4 pairs)
                __half2 b2[4];
                b2[0] = *(__half2*)&bv.x; b2[1] = *(__half2*)&bv.y;
                b2[2] = *(__half2*)&bv.z; b2[3] = *(__half2*)&bv.w;
                uint au[4] = { av.x, av.y, av.z, av.w };
                #pragma unroll
                for (int h = 0; h < 4; h++) {
                    uint lo = __byte_perm(au[h], 0, 0x1010);   // (h0,h0)
                    uint hi = __byte_perm(au[h], 0, 0x3232);   // (h1,h1)
                    __half2 alo = *(__half2*)&lo;
                    __half2 ahi = *(__half2*)&hi;
                    #pragma unroll
                    for (int jp = 0; jp < 4; jp++) {
                        acc2[2 * h][jp]     = __hfma2(alo, b2[jp], acc2[2 * h][jp]);
                        acc2[2 * h + 1][jp] = __hfma2(ahi, b2[jp], acc2[2 * h + 1][jp]);
                    }
                }
            }
            if ((dc & 7) == 7) {         // phase promote: fp16 -> fp32, reset
                #pragma unroll
                for (int i = 0; i < 8; i++)
                    #pragma unroll
                    for (int jp = 0; jp < 4; jp++) {
                        accf[i][2 * jp]     += __low2float(acc2[i][jp]);
                        accf[i][2 * jp + 1] += __high2float(acc2[i][jp]);
                        acc2[i][jp] = __float2half2_rn(0.f);
                    }
            }
        }

        // epilogue pass 1: per-token running-best update (shared, monotone)
        #pragma unroll
        for (int i = 0; i < 8; i++) {
            int tok = ty * 8 + i;
            float fi = f2s[tok];
            float lmin = 3.4e38f;
            #pragma unroll
            for (int j = 0; j < 8; j++) {
                float da = fmaf(-fi, accf[i][j], ens[tx * 8 + j]);
                if (da < lmin) lmin = da;
            }
            if (lmin < decf(bestuS[tok])) atomicMin(&bestuS[tok], encf(lmin));
        }
        __syncthreads();                 // bests visible to pass 2

        // epilogue pass 2: append codes within MARGIN of the global best-so-far
        #pragma unroll
        for (int i = 0; i < 8; i++) {
            int tok = ty * 8 + i;
            float fi = f2s[tok];
            float thr = decf(bestuS[tok]) + MARGIN;
            #pragma unroll
            for (int j = 0; j < 8; j++) {
                float da = fmaf(-fi, accf[i][j], ens[tx * 8 + j]);
                if (da < thr) {
                    int pos = atomicAdd(&cntS[tok], 1);
                    if (pos < CAP) candS[tok * CAP + pos] = k0 + tx * 8 + j;
                }
            }
        }
    }
    __syncthreads();

    // -------- exact fp32 rescue (reference rounding), 2 threads per token
    {
        int r = tid & 127, part = tid >> 7;
        int n = t0 + r;
        const float* zp = z + (size_t)(n >> 11) * DD * TT + (n & (TT - 1));
        float s1 = g_s1[n];
        int cnt = cntS[r];
        float bestd = 3.4e38f; int besti = 0x7fffffff;
        if (cnt <= CAP) {
            for (int q = part; q < cnt; q += 2) {
                int k = candS[r * CAP + q];
                const float* ep = emb + (size_t)k * DD;
                float dot = 0.f;
                #pragma unroll 8
                for (int d = 0; d < DD; d++) dot += zp[(size_t)d * TT] * ep[d];
                float c = s1 + g_enorm[k];
                float dist = c - 2.0f * dot;     // == fl(c - 2*dot), *2 exact
                if (dist < bestd || (dist == bestd && k < besti)) { bestd = dist; besti = k; }
            }
        } else {                                  // overflow: exact full scan
            for (int k = part; k < KK; k += 2) {
                const float* ep = emb + (size_t)k * DD;
                float dot = 0.f;
                #pragma unroll 8
                for (int d = 0; d < DD; d++) dot += zp[(size_t)d * TT] * ep[d];
                float c = s1 + g_enorm[k];
                float dist = c - 2.0f * dot;
                if (dist < bestd || (dist == bestd && k < besti)) { bestd = dist; besti = k; }
            }
        }
        rD[tid] = bestd; rI[tid] = besti;
    }
    __syncthreads();
    if (tid < 128) {
        float d0 = rD[tid], d1 = rD[tid + 128];
        int   i0 = rI[tid], i1 = rI[tid + 128];
        int best = (d1 < d0 || (d1 == d0 && i1 < i0)) ? i1 : i0;
        int n = t0 + tid;
        g_idx[n] = best;
        if (writeIdx) idxOutF[n] = (float)best;
    }
}

// ---------------------------------------------------------------------------
// Gather + straight-through output + loss partials (deterministic order)
__global__ void k_quant(const float* __restrict__ z, float* __restrict__ out) {
    __shared__ float red[256];
    size_t base = (size_t)blockIdx.x * 8192;
    float ls = 0.f;
    #pragma unroll 4
    for (int j = 0; j < 32; j++) {
        size_t i = base + threadIdx.x + (size_t)j * 256;
        int t = (int)(i & (TT - 1));
        int d = (int)((i >> 11) & (DD - 1));
        int b = (int)(i >> 19);
        int n = b * TT + t;
        float zv = z[i];
        float q  = g_embT[(size_t)d * KK + g_idx[n]];
        float diff = q - zv;
        out[i] = zv + diff;                // z + (q - z): reference rounding
        ls += diff * diff;
    }
    red[threadIdx.x] = ls;
    __syncthreads();
    #pragma unroll
    for (int o = 128; o > 0; o >>= 1) {
        if (threadIdx.x < o) red[threadIdx.x] += red[threadIdx.x + o];
        __syncthreads();
    }
    if (threadIdx.x == 0) g_partial[blockIdx.x] = red[0];
}

__global__ void k_final(float* out_loss, int doWrite) {
    __shared__ float red[256];
    float s = 0.f;
    #pragma unroll
    for (int j = 0; j < 4; j++) s += g_partial[threadIdx.x + j * 256];
    red[threadIdx.x] = s;
    __syncthreads();
    #pragma unroll
    for (int o = 128; o > 0; o >>= 1) {
        if (threadIdx.x < o) red[threadIdx.x] += red[threadIdx.x + o];
        __syncthreads();
    }
    if (threadIdx.x == 0 && doWrite)
        out_loss[0] = 1.25f * (red[0] / (float)NQ);
}

// ---------------------------------------------------------------------------
extern "C" void kernel_launch(void* const* d_in, const int* in_sizes, int n_in,
                              void* d_out, int out_size) {
    const float* z   = (const float*)d_in[0];
    const float* emb = (const float*)d_in[1];
    if (n_in >= 2 && in_sizes[0] == KK * DD && in_sizes[1] == NQ) {
        const float* tmp = z; z = emb; emb = tmp;   // defensive input-order swap
    }
    float* out = (float*)d_out;
    int writeTail = (out_size >= NQ + 1 + NN) ? 1 : 0;

    k_transpose<<<dim3(KK / 32, DD / 32), dim3(32, 8)>>>(emb);
    k_norms<<<KK / 8, 256>>>(emb);
    k_zero<<<1, 1>>>();
    k_semax<<<256, 256>>>(emb);
    k_prepA<<<NN / 128, 128>>>(z);
    k_prepB<<<KK / 256, 128>>>(emb);
    k_argmin_h<<<NN / 128, 256>>>(z, emb, out + NQ + 1, writeTail);
    k_quant<<<1024, 256>>>(z, out);
    k_final<<<1, 256>>>(out + NQ, writeTail);
}

// round 14
// speedup vs baseline: 18.3301x; 1.1291x over previous
#include <cuda_runtime.h>
#include <cuda_fp16.h>
#include <cstdint>

#define BB 16
#define DD 256
#define TT 2048
#define KK 8192
#define NN (BB*TT)          /* 32768 tokens  */
#define NQ (BB*DD*TT)       /* 8388608 elems */

typedef unsigned int uint;

// ---------------------------------------------------------------------------
// Scratch (static __device__ arrays: allocation-free per harness rules)
__device__ __align__(128) uint g_zh2[DD * NN];      // 32MB: z fp16 dup (h,h), [d][token]
__device__ __align__(128) uint g_eh[DD * KK / 2];   //  4MB: emb fp16 pairs, [d][kpair]
__device__ float g_embT[DD*KK];    // emb transposed [D][K] (for k_quant + prepB)
__device__ float g_enorm[KK];      // ||e_k||^2 (exact fp32)
__device__ float g_s1[NN];         // ||z_n||^2 (sequential-d fp32)
__device__ float g_f2[NN];         // 2*sz_n*se
__device__ uint  g_seU;            // max|emb| as float bits
__device__ int   g_idx[NN];        // argmin per token
__device__ float g_partial[1024];  // loss partials

// order-preserving float<->uint (monotonic; atomicMin-able)
__device__ __forceinline__ uint encf(float f) {
    uint b = __float_as_uint(f);
    return (b & 0x80000000u) ? ~b : (b | 0x80000000u);
}
__device__ __forceinline__ float decf(uint u) {
    return (u & 0x80000000u) ? __uint_as_float(u & 0x7fffffffu)
                             : __uint_as_float(~u);
}
__device__ __forceinline__ uint s2u(const void* p) {
    uint a;
    asm("{ .reg .u64 t; cvta.to.shared.u64 t, %1; cvt.u32.u64 %0, t; }"
        : "=r"(a) : "l"(p));
    return a;
}
__device__ __forceinline__ void cpa16(uint dst, const void* src) {
    asm volatile("cp.async.cg.shared.global [%0], [%1], 16;"
                 :: "r"(dst), "l"(src) : "memory");
}
__device__ __forceinline__ void cpcommit() {
    asm volatile("cp.async.commit_group;" ::: "memory");
}

// ---------------------------------------------------------------------------
// emb [K,D] -> embT [D,K]
__global__ void k_transpose(const float* __restrict__ emb) {
    __shared__ float tile[32][33];
    int k0 = blockIdx.x * 32, d0 = blockIdx.y * 32;
    int tx = threadIdx.x, ty = threadIdx.y;
    #pragma unroll
    for (int i = 0; i < 32; i += 8)
        tile[ty + i][tx] = emb[(size_t)(k0 + ty + i) * DD + d0 + tx];
    __syncthreads();
    #pragma unroll
    for (int i = 0; i < 32; i += 8)
        g_embT[(size_t)(d0 + ty + i) * KK + k0 + tx] = tile[tx][ty + i];
}

// per-code squared norms (UNCHANGED from the rel_err=0 kernel)
__global__ void k_norms(const float* __restrict__ emb) {
    int r = blockIdx.x * 8 + (threadIdx.x >> 5);
    int lane = threadIdx.x & 31;
    float s = 0.f;
    for (int i = lane; i < DD; i += 32) {
        float v = emb[(size_t)r * DD + i];
        s += v * v;
    }
    #pragma unroll
    for (int o = 16; o > 0; o >>= 1) s += __shfl_xor_sync(0xffffffffu, s, o);
    if (lane == 0) g_enorm[r] = s;
}

__global__ void k_zero() { g_seU = 0u; }

// global max|emb| (max is order-invariant -> deterministic)
__global__ void k_semax(const float* __restrict__ emb) {
    __shared__ float red[256];
    float m = 0.f;
    for (int i = blockIdx.x * 256 + threadIdx.x; i < KK * DD; i += 256 * 256)
        m = fmaxf(m, fabsf(emb[i]));
    red[threadIdx.x] = m;
    __syncthreads();
    #pragma unroll
    for (int o = 128; o > 0; o >>= 1) {
        if (threadIdx.x < o) red[threadIdx.x] = fmaxf(red[threadIdx.x], red[threadIdx.x + o]);
        __syncthreads();
    }
    if (threadIdx.x == 0) atomicMax(&g_seU, __float_as_uint(red[0]));
}

// z -> scaled fp16 dup (h,h) [d][token]; ||z||^2 sequential-d fp32; f2 scale
__global__ void k_prepA(const float* __restrict__ z) {
    int n = blockIdx.x * 128 + threadIdx.x;
    const float* zp = z + (size_t)(n >> 11) * DD * TT + (n & (TT - 1));
    float se = __uint_as_float(g_seU);
    float s1 = 0.f, mx = 0.f;
    for (int d0 = 0; d0 < DD; d0 += 8) {
        float v[8];
        #pragma unroll
        for (int u = 0; u < 8; u++) v[u] = zp[(size_t)(d0 + u) * TT];
        #pragma unroll
        for (int u = 0; u < 8; u++) s1 += v[u] * v[u];
        #pragma unroll
        for (int u = 0; u < 8; u++) mx = fmaxf(mx, fabsf(v[u]));
    }
    float sz = fmaxf(mx, 1e-30f);
    float qs = 1.0f / sz;
    for (int d = 0; d < DD; d++) {
        __half h = __float2half_rn(zp[(size_t)d * TT] * qs);
        uint hb = (uint)(*(unsigned short*)&h);
        g_zh2[(size_t)d * NN + n] = hb | (hb << 16);
    }
    g_s1[n] = s1;
    g_f2[n] = 2.0f * sz * se;
}

// emb -> scaled fp16 pairs [d][kpair] (reads embT: coalesced)
__global__ void k_prepB(const float* /*emb*/) {
    int jp = blockIdx.x * 128 + threadIdx.x;       // 0..4095 code pairs
    float qs = 1.0f / __uint_as_float(g_seU);
    for (int d = 0; d < DD; d++) {
        float e0 = g_embT[(size_t)d * KK + 2 * jp];
        float e1 = g_embT[(size_t)d * KK + 2 * jp + 1];
        __half2 h = __floats2half2_rn(e0 * qs, e1 * qs);
        g_eh[(size_t)d * (KK / 2) + jp] = *(uint*)&h;
    }
}

// ---------------------------------------------------------------------------
// HFMA2 pass-1: 32 tokens/block x all 8192 codes. occupancy 2, A resident,
// B cp.async 3-stage ring. Two-phase candidate epilogue + exact fp32 rescue.
#define CAP 32
#define MARGIN 2.5e-4f
#define NSTG 512                     /* 64 ct x 8 d-stages */

#define SM_A    0                    /* [256 d][32 tok] dup uints, 32KB */
#define SM_B    32768                /* 3 x [32 d][64 pair] uints, 24KB */
#define SM_BEST 57344
#define SM_CNT  57472
#define SM_CAND 57600                /* 32 x CAP ints */
#define SM_RD   61696
#define SM_RI   62720
#define SMEMSZ  63744

__global__ __launch_bounds__(256, 2)
void k_argmin_h2(const float* __restrict__ z, const float* __restrict__ emb,
                 float* __restrict__ idxOutF, int writeIdx) {
    extern __shared__ char sm[];
    uint sb = s2u(sm);
    int tid = threadIdx.x;
    int ty = tid >> 5, tx = tid & 31;      // 8 x 32 thread grid; tile 4 tok x 4 codes
    int tile = blockIdx.x;
    int t0 = tile * 32;

    uint* sBest = (uint*)(sm + SM_BEST);
    int*  sCnt  = (int*)(sm + SM_CNT);
    int*  sCand = (int*)(sm + SM_CAND);

    if (tid < 32) { sBest[tid] = encf(3.4e38f); sCnt[tid] = 0; }

    float f2r[4];
    #pragma unroll
    for (int i = 0; i < 4; i++) f2r[i] = g_f2[t0 + ty * 4 + i];

    // A resident load: row d = tid, 32 dup-uints (=128B)
    {
        const char* src = (const char*)(g_zh2 + (size_t)tid * NN + t0);
        uint dst = sb + SM_A + tid * 128;
        #pragma unroll
        for (int j = 0; j < 8; j++) cpa16(dst + j * 16, src + j * 16);
    }
    // B stage loader: stage S -> ct=S>>3, dbase=(S&7)*32, buf=S%3
    auto loadB = [&](int S) {
        int ct = S >> 3, dbase = (S & 7) * 32, buf = S % 3;
        int rr = tid >> 3, c8 = (tid & 7) * 8;
        const char* src = (const char*)(g_eh + (size_t)(dbase + rr) * (KK / 2) + ct * 64 + c8);
        uint dst = sb + SM_B + buf * 8192 + rr * 256 + c8 * 4;
        cpa16(dst, src);
        cpa16(dst + 16, src + 16);
    };
    loadB(0); cpcommit();                  // group 0: A + stage0
    loadB(1); cpcommit();                  // group 1: stage1

    __half2 acc2[4][2];
    float   accf[4][4];
    #pragma unroll
    for (int i = 0; i < 4; i++) {
        acc2[i][0] = __float2half2_rn(0.f);
        acc2[i][1] = __float2half2_rn(0.f);
        #pragma unroll
        for (int j = 0; j < 4; j++) accf[i][j] = 0.f;
    }

    for (int S = 0; S < NSTG; S++) {
        if (S < NSTG - 1)
            asm volatile("cp.async.wait_group 1;" ::: "memory");
        else
            asm volatile("cp.async.wait_group 0;" ::: "memory");
        __syncthreads();                   // stage S visible; all done with S-1
        if (S + 2 < NSTG) { loadB(S + 2); cpcommit(); }

        int dbase = (S & 7) * 32, buf = S % 3;
        uint aAddr = sb + SM_A + dbase * 128 + ty * 16;
        uint bAddr = sb + SM_B + buf * 8192 + tx * 8;
        #pragma unroll 8
        for (int dd = 0; dd < 32; dd++) {
            uint4 av = *(uint4*)(sm + (aAddr - sb) + dd * 128);
            uint2 bv = *(uint2*)(sm + (bAddr - sb) + dd * 256);
            __half2 b0 = *(__half2*)&bv.x, b1 = *(__half2*)&bv.y;
            #pragma unroll
            for (int i = 0; i < 4; i++) {
                __half2 ai = *(__half2*)(((uint*)&av) + i);
                acc2[i][0] = __hfma2(ai, b0, acc2[i][0]);
                acc2[i][1] = __hfma2(ai, b1, acc2[i][1]);
            }
        }
        // phase promote (every 32 d): fp16 -> fp32
        #pragma unroll
        for (int i = 0; i < 4; i++) {
            accf[i][0] += __low2float(acc2[i][0]);
            accf[i][1] += __high2float(acc2[i][0]);
            accf[i][2] += __low2float(acc2[i][1]);
            accf[i][3] += __high2float(acc2[i][1]);
            acc2[i][0] = __float2half2_rn(0.f);
            acc2[i][1] = __float2half2_rn(0.f);
        }

        if ((S & 7) == 7) {                // ct complete: epilogue
            int ct = S >> 3;
            int kbase = ct * 128 + tx * 4;
            float4 en = *(const float4*)&g_enorm[kbase];
            float enj[4] = { en.x, en.y, en.z, en.w };
            // pass 1: per-token running best (monotone shared atomicMin)
            #pragma unroll
            for (int i = 0; i < 4; i++) {
                int tok = ty * 4 + i;
                float lmin = 3.4e38f;
                #pragma unroll
                for (int j = 0; j < 4; j++) {
                    float da = fmaf(-f2r[i], accf[i][j], enj[j]);
                    if (da < lmin) lmin = da;
                }
                if (lmin < decf(sBest[tok])) atomicMin(&sBest[tok], encf(lmin));
            }
            __syncthreads();               // bests visible
            // pass 2: append within MARGIN of global-running best
            #pragma unroll
            for (int i = 0; i < 4; i++) {
                int tok = ty * 4 + i;
                float thr = decf(sBest[tok]) + MARGIN;
                #pragma unroll
                for (int j = 0; j < 4; j++) {
                    float da = fmaf(-f2r[i], accf[i][j], enj[j]);
                    if (da < thr) {
                        int pos = atomicAdd(&sCnt[tok], 1);
                        if (pos < CAP) sCand[tok * CAP + pos] = kbase + j;
                    }
                    accf[i][j] = 0.f;
                }
            }
            // next stage-loop sync orders pass2 reads vs next ct's pass1 writes
        }
    }
    __syncthreads();

    // -------- exact fp32 rescue (reference rounding), 8 threads per token
    float* rD = (float*)(sm + SM_RD);
    int*   rI = (int*)(sm + SM_RI);
    {
        int r = tid & 31, part = tid >> 5;
        int n = t0 + r;
        const float* zp = z + (size_t)(n >> 11) * DD * TT + (n & (TT - 1));
        float s1 = g_s1[n];
        int cnt = sCnt[r];
        float bestd = 3.4e38f; int besti = 0x7fffffff;
        if (cnt <= CAP) {
            for (int q = part; q < cnt; q += 8) {
                int k = sCand[r * CAP + q];
                const float* ep = emb + (size_t)k * DD;
                float dot = 0.f;
                #pragma unroll 8
                for (int d = 0; d < DD; d++) dot += zp[(size_t)d * TT] * ep[d];
                float c = s1 + g_enorm[k];
                float dist = c - 2.0f * dot;     // == fl(c - 2*dot), *2 exact
                if (dist < bestd || (dist == bestd && k < besti)) { bestd = dist; besti = k; }
            }
        } else {                                  // overflow: exact full scan
            for (int k = part; k < KK; k += 8) {
                const float* ep = emb + (size_t)k * DD;
                float dot = 0.f;
                #pragma unroll 8
                for (int d = 0; d < DD; d++) dot += zp[(size_t)d * TT] * ep[d];
                float c = s1 + g_enorm[k];
                float dist = c - 2.0f * dot;
                if (dist < bestd || (dist == bestd && k < besti)) { bestd = dist; besti = k; }
            }
        }
        rD[tid] = bestd; rI[tid] = besti;
    }
    __syncthreads();
    if (tid < 32) {
        float best = rD[tid]; int besti = rI[tid];
        #pragma unroll
        for (int p = 1; p < 8; p++) {
            float d = rD[p * 32 + tid]; int ii = rI[p * 32 + tid];
            if (d < best || (d == best && ii < besti)) { best = d; besti = ii; }
        }
        int n = t0 + tid;
        g_idx[n] = besti;
        if (writeIdx) idxOutF[n] = (float)besti;
    }
}

// ---------------------------------------------------------------------------
// Gather + straight-through output + loss partials (deterministic order)
__global__ void k_quant(const float* __restrict__ z, float* __restrict__ out) {
    __shared__ float red[256];
    size_t base = (size_t)blockIdx.x * 8192;
    float ls = 0.f;
    #pragma unroll 4
    for (int j = 0; j < 32; j++) {
        size_t i = base + threadIdx.x + (size_t)j * 256;
        int t = (int)(i & (TT - 1));
        int d = (int)((i >> 11) & (DD - 1));
        int b = (int)(i >> 19);
        int n = b * TT + t;
        float zv = z[i];
        float q  = g_embT[(size_t)d * KK + g_idx[n]];
        float diff = q - zv;
        out[i] = zv + diff;                // z + (q - z): reference rounding
        ls += diff * diff;
    }
    red[threadIdx.x] = ls;
    __syncthreads();
    #pragma unroll
    for (int o = 128; o > 0; o >>= 1) {
        if (threadIdx.x < o) red[threadIdx.x] += red[threadIdx.x + o];
        __syncthreads();
    }
    if (threadIdx.x == 0) g_partial[blockIdx.x] = red[0];
}

__global__ void k_final(float* out_loss, int doWrite) {
    __shared__ float red[256];
    float s = 0.f;
    #pragma unroll
    for (int j = 0; j < 4; j++) s += g_partial[threadIdx.x + j * 256];
    red[threadIdx.x] = s;
    __syncthreads();
    #pragma unroll
    for (int o = 128; o > 0; o >>= 1) {
        if (threadIdx.x < o) red[threadIdx.x] += red[threadIdx.x + o];
        __syncthreads();
    }
    if (threadIdx.x == 0 && doWrite)
        out_loss[0] = 1.25f * (red[0] / (float)NQ);
}

// ---------------------------------------------------------------------------
extern "C" void kernel_launch(void* const* d_in, const int* in_sizes, int n_in,
                              void* d_out, int out_size) {
    const float* z   = (const float*)d_in[0];
    const float* emb = (const float*)d_in[1];
    if (n_in >= 2 && in_sizes[0] == KK * DD && in_sizes[1] == NQ) {
        const float* tmp = z; z = emb; emb = tmp;   // defensive input-order swap
    }
    float* out = (float*)d_out;
    int writeTail = (out_size >= NQ + 1 + NN) ? 1 : 0;

    static int attrSet = 0;
    if (!attrSet) {
        cudaFuncSetAttribute(k_argmin_h2,
                             cudaFuncAttributeMaxDynamicSharedMemorySize, SMEMSZ);
        attrSet = 1;
    }

    k_transpose<<<dim3(KK / 32, DD / 32), dim3(32, 8)>>>(emb);
    k_norms<<<KK / 8, 256>>>(emb);
    k_zero<<<1, 1>>>();
    k_semax<<<256, 256>>>(emb);
    k_prepA<<<NN / 128, 128>>>(z);
    k_prepB<<<KK / 256, 128>>>(emb);
    k_argmin_h2<<<NN / 32, 256, SMEMSZ>>>(z, emb, out + NQ + 1, writeTail);
    k_quant<<<1024, 256>>>(z, out);
    k_final<<<1, 256>>>(out + NQ, writeTail);
}